// round 11
// baseline (speedup 1.0000x reference)
#include <cuda_runtime.h>
#include <cuda_fp16.h>
#include <math.h>
#include <stdint.h>

// ---------------- problem constants ----------------
#define SEQ_LEN   65536
#define NN        256
#define NC        32
#define LW        16
#define NL        14
#define NF        200
#define ROWS      64       // M per CTA (2 CTAs/SM)
#define NTHREADS  256      // 8 warps: 4 row-groups x 2 n-halves
#define AS        264      // A row stride in fp16 elems (528 B) -> conflict-free ldmatrix

// ---------------- smem map (bytes) ----------------
#define OFF_ACTS  0
#define OFF_XS    1024
#define OFF_BP    2048
#define BROW      40                        // u32 words per r-row
#define BHALF     (64 * BROW * 4)           // 10240 B (hi or lo)
#define BBUF      (2 * BHALF)               // 20480 B
#define OFF_AHI   (OFF_BP + 2 * BBUF)       // 43008
#define ABYTES    (ROWS * AS * 2)           // 33792
#define OFF_ALO   (OFF_AHI + ABYTES)        // 76800
#define SMEM_BYTES (OFF_ALO + ABYTES)       // 110592  -> 2 CTAs/SM

// ---------------- helpers ----------------
__device__ __forceinline__ uint32_t smem_u32(const void* p) {
    uint32_t a;
    asm("{ .reg .u64 t; cvta.to.shared.u64 t, %1; cvt.u32.u64 %0, t; }" : "=r"(a) : "l"(p));
    return a;
}
__device__ __forceinline__ void ldsm_x4(uint32_t a[4], uint32_t addr) {
    asm volatile("ldmatrix.sync.aligned.m8n8.x4.shared.b16 {%0,%1,%2,%3}, [%4];"
        : "=r"(a[0]), "=r"(a[1]), "=r"(a[2]), "=r"(a[3]) : "r"(addr));
}
__device__ __forceinline__ void mma16816(float c[4], const uint32_t a[4], uint32_t b0, uint32_t b1) {
    asm volatile("mma.sync.aligned.m16n8k16.row.col.f32.f16.f16.f32 "
        "{%0,%1,%2,%3}, {%4,%5,%6,%7}, {%8,%9}, {%0,%1,%2,%3};"
        : "+f"(c[0]), "+f"(c[1]), "+f"(c[2]), "+f"(c[3])
        : "r"(a[0]), "r"(a[1]), "r"(a[2]), "r"(a[3]), "r"(b0), "r"(b1));
}
__device__ __forceinline__ void split16(float v, uint16_t& h, uint16_t& l) {
    __half hh = __float2half_rn(v);
    float  r  = v - __half2float(hh);
    __half ll = __float2half_rn(r);
    h = __half_as_ushort(hh);
    l = __half_as_ushort(ll);
}
__device__ __forceinline__ float ex2a(float x) {
    float r; asm("ex2.approx.f32 %0, %1;" : "=f"(r) : "f"(x)); return r;
}
__device__ __forceinline__ float rcpa(float x) {
    float r; asm("rcp.approx.f32 %0, %1;" : "=f"(r) : "f"(x)); return r;
}
__device__ __forceinline__ float actf(int aid, float z) {
    if (aid == 0) return z;
    if (aid == 2) return fmaxf(z, 0.f);
    if (aid == 1) {                       // tanh(z) = 1 - 2/(1+e^{2z})
        float t = ex2a(z * 2.8853900817779268f);
        return fmaf(-2.f, rcpa(t + 1.f), 1.f);
    }
    float t = ex2a(-z * 1.4426950408889634f);      // sigmoid
    return rcpa(1.f + t);
}
__device__ __forceinline__ float readA(const char* hi, const char* lo, int m, int node) {
    uint32_t b = (uint32_t)m * (AS * 2) + (uint32_t)node * 2;
    return __half2float(*(const __half*)(hi + b)) + __half2float(*(const __half*)(lo + b));
}
// packed-B byte offset for parent p, col n (within hi or lo half)
__device__ __forceinline__ uint32_t bOff(int p, int n) {
    int kk = p >> 1, parity = p & 1;
    int r  = ((kk >> 3) << 2) + (kk & 3);
    int h  = (kk >> 2) & 1;
    return (uint32_t)((r * BROW + n * 2 + h) << 2) + (uint32_t)(parity << 1);
}

// Fully-unrolled MMA loop for one layer; 6 accumulator chains (even/odd j x hh/hl/lh).
template<int NCH>
__device__ __forceinline__ void layer_mma(float chh[2][4], float chl[2][4], float clh[2][4],
                                          uint32_t a_addr, const char* bp, uint32_t bwoff) {
    #pragma unroll
    for (int j = 0; j < NCH; ++j) {
        uint32_t ahi[4], alo[4];
        ldsm_x4(ahi, a_addr + (uint32_t)j * 32);
        ldsm_x4(alo, a_addr + ABYTES + (uint32_t)j * 32);
        uint2 bh = *(const uint2*)(bp + (uint32_t)j * (4 * BROW * 4) + bwoff);
        uint2 bl = *(const uint2*)(bp + BHALF + (uint32_t)j * (4 * BROW * 4) + bwoff);
        const int s = j & 1;
        mma16816(chh[s], ahi, bh.x, bh.y);
        mma16816(chl[s], ahi, bl.x, bl.y);
        mma16816(clh[s], alo, bh.x, bh.y);
    }
}

__global__ __launch_bounds__(NTHREADS, 2)
void scm_kernel(const float* __restrict__ causes,
                const float* __restrict__ W,
                const float* __restrict__ eps,
                const int*   __restrict__ act_ids,
                const int*   __restrict__ x_idx,
                const int*   __restrict__ y_idx_p,
                float*       __restrict__ out)
{
    extern __shared__ char smem[];
    const uint32_t sb = smem_u32(smem);
    int*  acts = (int*)(smem + OFF_ACTS);
    int*  xs   = (int*)(smem + OFF_XS);
    char* Ahi  = smem + OFF_AHI;
    char* Alo  = smem + OFF_ALO;

    const int tid  = threadIdx.x;
    const int lane = tid & 31;
    const int g    = lane >> 2;
    const int tig  = lane & 3;
    const int wid  = tid >> 5;
    const int rg   = wid & 3;
    const int nh   = wid >> 2;
    const int R    = rg * 16;
    const int row0 = blockIdx.x * ROWS;

    if (tid < NN) acts[tid] = act_ids[tid];
    if (tid < NF) xs[tid]   = x_idx[tid];

    // ---- roots: A[:, 0:32] = hi/lo split of clip(causes, -5, 5) ----
    {
        int m = tid >> 2, q = tid & 3;
        const float4* c4 = (const float4*)(causes + (size_t)(row0 + m) * NC + q * 8);
        float4 a = c4[0], b = c4[1];
        float v[8] = { a.x,a.y,a.z,a.w, b.x,b.y,b.z,b.w };
        uint32_t whi[4], wlo[4];
        #pragma unroll
        for (int i = 0; i < 4; ++i) {
            uint16_t h0, l0, h1, l1;
            float v0 = fminf(fmaxf(v[2*i],   -5.f), 5.f);
            float v1 = fminf(fmaxf(v[2*i+1], -5.f), 5.f);
            split16(v0, h0, l0); split16(v1, h1, l1);
            whi[i] = (uint32_t)h0 | ((uint32_t)h1 << 16);
            wlo[i] = (uint32_t)l0 | ((uint32_t)l1 << 16);
        }
        uint32_t base = (uint32_t)m * (AS * 2) + (uint32_t)q * 16;
        *(uint4*)(Ahi + base) = make_uint4(whi[0], whi[1], whi[2], whi[3]);
        *(uint4*)(Alo + base) = make_uint4(wlo[0], wlo[1], wlo[2], wlo[3]);
    }

    // ---- pack B(0) directly ----
    {
        char* bHi = smem + OFF_BP;
        char* bLo = bHi + BHALF;
        for (int e = tid; e < NC * 16; e += NTHREADS) {
            int p = e >> 4, n = e & 15;
            uint16_t h, l; split16(W[(size_t)p * NN + NC + n], h, l);
            uint32_t byte = bOff(p, n);
            *(uint16_t*)(bHi + byte) = h;
            *(uint16_t*)(bLo + byte) = l;
        }
    }
    __syncthreads();

    const uint32_t a_addr = sb + OFF_AHI
                          + (uint32_t)(R + (lane & 15)) * (AS * 2)
                          + (uint32_t)((lane >> 4) * 8) * 2;
    const int bcol = nh * 8 + g;
    const uint32_t bwoff = (uint32_t)(tig * BROW + bcol * 2) * 4;

    for (int k = 0; k < NL; ++k) {
        const int nb   = NC + k * LW;
        const int nch  = nb >> 4;
        const char* bp = smem + OFF_BP + (k & 1) * BBUF;

        // W(k+1) prefetch into registers (static chunk->thread identity map)
        float4 wreg[4];
        const int nchunksN = (k < NL - 1) ? (nb + LW) * 4 : 0;
        #pragma unroll
        for (int c2 = 0; c2 < 4; ++c2) {
            int c = tid + c2 * NTHREADS;
            if (c < nchunksN)
                wreg[c2] = *(const float4*)(W + (size_t)(c >> 2) * NN + (nb + LW) + (c & 3) * 4);
        }

        // eps LDG early (consumed in epilogue)
        const int col0 = nb + nh * 8 + 2 * tig;
        float2 ev0 = *(const float2*)(eps + (size_t)(row0 + R + g)     * NN + col0);
        float2 ev1 = *(const float2*)(eps + (size_t)(row0 + R + g + 8) * NN + col0);

        // --- fully-unrolled MMA loop, 6 accumulator chains ---
        float chh[2][4] = {{0,0,0,0},{0,0,0,0}};
        float chl[2][4] = {{0,0,0,0},{0,0,0,0}};
        float clh[2][4] = {{0,0,0,0},{0,0,0,0}};
        switch (nch) {
            case 2:  layer_mma<2>(chh, chl, clh, a_addr, bp, bwoff); break;
            case 3:  layer_mma<3>(chh, chl, clh, a_addr, bp, bwoff); break;
            case 4:  layer_mma<4>(chh, chl, clh, a_addr, bp, bwoff); break;
            case 5:  layer_mma<5>(chh, chl, clh, a_addr, bp, bwoff); break;
            case 6:  layer_mma<6>(chh, chl, clh, a_addr, bp, bwoff); break;
            case 7:  layer_mma<7>(chh, chl, clh, a_addr, bp, bwoff); break;
            case 8:  layer_mma<8>(chh, chl, clh, a_addr, bp, bwoff); break;
            case 9:  layer_mma<9>(chh, chl, clh, a_addr, bp, bwoff); break;
            case 10: layer_mma<10>(chh, chl, clh, a_addr, bp, bwoff); break;
            case 11: layer_mma<11>(chh, chl, clh, a_addr, bp, bwoff); break;
            case 12: layer_mma<12>(chh, chl, clh, a_addr, bp, bwoff); break;
            case 13: layer_mma<13>(chh, chl, clh, a_addr, bp, bwoff); break;
            case 14: layer_mma<14>(chh, chl, clh, a_addr, bp, bwoff); break;
            default: layer_mma<15>(chh, chl, clh, a_addr, bp, bwoff); break;
        }

        // convert register-held W(k+1) -> packed B((k+1)&1)
        if (k < NL - 1) {
            char* bHi = smem + OFF_BP + ((k + 1) & 1) * BBUF;
            char* bLo = bHi + BHALF;
            #pragma unroll
            for (int c2 = 0; c2 < 4; ++c2) {
                int c = tid + c2 * NTHREADS;
                if (c < nchunksN) {
                    int p = c >> 2, s = c & 3;
                    float vv[4] = { wreg[c2].x, wreg[c2].y, wreg[c2].z, wreg[c2].w };
                    #pragma unroll
                    for (int i = 0; i < 4; ++i) {
                        uint16_t h, l; split16(vv[i], h, l);
                        uint32_t byte = bOff(p, s * 4 + i);
                        *(uint16_t*)(bHi + byte) = h;
                        *(uint16_t*)(bLo + byte) = l;
                    }
                }
            }
        }

        // epilogue: z = sum(chains) + eps, activation, hi/lo split, store back to A
        {
            const int aid0 = acts[col0], aid1 = acts[col0 + 1];
            float z0 = (chh[0][0]+chh[1][0]) + (chl[0][0]+chl[1][0]) + (clh[0][0]+clh[1][0]) + ev0.x;
            float z1 = (chh[0][1]+chh[1][1]) + (chl[0][1]+chl[1][1]) + (clh[0][1]+clh[1][1]) + ev0.y;
            float z2 = (chh[0][2]+chh[1][2]) + (chl[0][2]+chl[1][2]) + (clh[0][2]+clh[1][2]) + ev1.x;
            float z3 = (chh[0][3]+chh[1][3]) + (chl[0][3]+chl[1][3]) + (clh[0][3]+clh[1][3]) + ev1.y;
            float a0 = actf(aid0, z0), a1 = actf(aid1, z1);
            float a2 = actf(aid0, z2), a3 = actf(aid1, z3);
            uint16_t h0,l0,h1,l1,h2,l2,h3,l3;
            split16(a0,h0,l0); split16(a1,h1,l1); split16(a2,h2,l2); split16(a3,h3,l3);
            uint32_t b0 = (uint32_t)(R + g)     * (AS * 2) + (uint32_t)col0 * 2;
            uint32_t b1 = (uint32_t)(R + g + 8) * (AS * 2) + (uint32_t)col0 * 2;
            *(uint32_t*)(Ahi + b0) = (uint32_t)h0 | ((uint32_t)h1 << 16);
            *(uint32_t*)(Alo + b0) = (uint32_t)l0 | ((uint32_t)l1 << 16);
            *(uint32_t*)(Ahi + b1) = (uint32_t)h2 | ((uint32_t)h3 << 16);
            *(uint32_t*)(Alo + b1) = (uint32_t)l2 | ((uint32_t)l3 << 16);
        }
        __syncthreads();   // publish A cols + B(k+1)
    }

    // ---- outputs ----
    const int yidx = y_idx_p ? *y_idx_p : (NN - 1);
    float* Xout = out;
    float* yout = out + (size_t)SEQ_LEN * NF;

    if (tid < ROWS) {
        float v = readA(Ahi, Alo, tid, yidx);
        if (v != v) v = 0.f;
        yout[row0 + tid] = v;
    }
    for (int idx = tid; idx < ROWS * NF; idx += NTHREADS) {
        int r = idx / NF, j2 = idx - r * NF;
        float v = readA(Ahi, Alo, r, xs[j2]);
        if (v != v) v = 0.f;
        v = fminf(fmaxf(v, -15.f), 15.f);
        Xout[(size_t)(row0 + r) * NF + j2] = v;
    }
}

extern "C" void kernel_launch(void* const* d_in, const int* in_sizes, int n_in,
                              void* d_out, int out_size)
{
    const float* causes  = (const float*)d_in[0];
    const float* W       = (const float*)d_in[1];
    const float* eps     = (const float*)d_in[2];
    const int*   act_ids = (const int*)d_in[3];
    const int*   x_idx   = (const int*)d_in[4];
    const int*   y_idx_p = (n_in > 5) ? (const int*)d_in[5] : nullptr;
    float*       out     = (float*)d_out;

    cudaFuncSetAttribute(scm_kernel, cudaFuncAttributeMaxDynamicSharedMemorySize, SMEM_BYTES);

    scm_kernel<<<SEQ_LEN / ROWS, NTHREADS, SMEM_BYTES>>>(
        causes, W, eps, act_ids, x_idx, y_idx_p, out);
    (void)in_sizes; (void)out_size;
}

// round 12
// speedup vs baseline: 1.2327x; 1.2327x over previous
#include <cuda_runtime.h>
#include <cuda_fp16.h>
#include <math.h>
#include <stdint.h>

// ---------------- problem constants ----------------
#define SEQ_LEN   65536
#define NN        256
#define NC        32
#define LW        16
#define NL        14
#define NF        200
#define ROWS      64       // M per CTA (2 CTAs/SM)
#define NTHREADS  256      // 8 warps: 4 row-groups x 2 n-halves
#define AS        264      // A row stride in fp16 elems (528 B) -> conflict-free ldmatrix

// ---------------- packed-B layout ----------------
// Per layer: rows r = j*4 + tig (4 per K-chunk), BROW=40 u32 words per row:
//   word[h*16 + n] = fp16 pair (parents p=2*kk, 2*kk+1), kk = j*8 + tig + 4*h, col n.
// hi half at [0, BHALF), lo half at [BHALF, 2*BHALF).
#define BROW      40
#define BHALF     (64 * BROW * 4)           // 10240 B
#define BBUF      (2 * BHALF)               // 20480 B per layer image

// ---------------- smem map (bytes) ----------------
#define OFF_ACTS  0
#define OFF_XS    1024
#define OFF_BP    2048
#define OFF_AHI   (OFF_BP + 2 * BBUF)       // 43008
#define ABYTES    (ROWS * AS * 2)           // 33792
#define OFF_ALO   (OFF_AHI + ABYTES)        // 76800
#define SMEM_BYTES (OFF_ALO + ABYTES)       // 110592  -> 2 CTAs/SM

// Pre-packed W images (hi/lo fp16), written by pack_kernel, read via cp.async.
__device__ __align__(16) unsigned char g_packedW[NL * BBUF];

// ---------------- helpers ----------------
__device__ __forceinline__ uint32_t smem_u32(const void* p) {
    uint32_t a;
    asm("{ .reg .u64 t; cvta.to.shared.u64 t, %1; cvt.u32.u64 %0, t; }" : "=r"(a) : "l"(p));
    return a;
}
__device__ __forceinline__ void ldsm_x4(uint32_t a[4], uint32_t addr) {
    asm volatile("ldmatrix.sync.aligned.m8n8.x4.shared.b16 {%0,%1,%2,%3}, [%4];"
        : "=r"(a[0]), "=r"(a[1]), "=r"(a[2]), "=r"(a[3]) : "r"(addr));
}
__device__ __forceinline__ void mma16816(float c[4], const uint32_t a[4], uint32_t b0, uint32_t b1) {
    asm volatile("mma.sync.aligned.m16n8k16.row.col.f32.f16.f16.f32 "
        "{%0,%1,%2,%3}, {%4,%5,%6,%7}, {%8,%9}, {%0,%1,%2,%3};"
        : "+f"(c[0]), "+f"(c[1]), "+f"(c[2]), "+f"(c[3])
        : "r"(a[0]), "r"(a[1]), "r"(a[2]), "r"(a[3]), "r"(b0), "r"(b1));
}
__device__ __forceinline__ void split16(float v, uint16_t& h, uint16_t& l) {
    __half hh = __float2half_rn(v);
    float  r  = v - __half2float(hh);
    __half ll = __float2half_rn(r);
    h = __half_as_ushort(hh);
    l = __half_as_ushort(ll);
}
__device__ __forceinline__ float ex2a(float x) {
    float r; asm("ex2.approx.f32 %0, %1;" : "=f"(r) : "f"(x)); return r;
}
__device__ __forceinline__ float rcpa(float x) {
    float r; asm("rcp.approx.f32 %0, %1;" : "=f"(r) : "f"(x)); return r;
}
__device__ __forceinline__ float actf(int aid, float z) {
    if (aid == 0) return z;
    if (aid == 2) return fmaxf(z, 0.f);
    if (aid == 1) {                       // tanh(z) = 1 - 2/(1+e^{2z})
        float t = ex2a(z * 2.8853900817779268f);
        return fmaf(-2.f, rcpa(t + 1.f), 1.f);
    }
    float t = ex2a(-z * 1.4426950408889634f);      // sigmoid
    return rcpa(1.f + t);
}
__device__ __forceinline__ float readA(const char* hi, const char* lo, int m, int node) {
    uint32_t b = (uint32_t)m * (AS * 2) + (uint32_t)node * 2;
    return __half2float(*(const __half*)(hi + b)) + __half2float(*(const __half*)(lo + b));
}

// ---------------- pack kernel: W -> g_packedW (hi/lo fp16, B layout) ----------------
__global__ void pack_kernel(const float* __restrict__ W) {
    const int k = blockIdx.y;
    const int e = blockIdx.x * 256 + threadIdx.x;   // e = p*16 + n
    const int nb = NC + k * LW;                     // K (= parent count) for layer k
    if (e >= nb * 16) return;
    const int p = e >> 4, n = e & 15;
    uint16_t h, l;
    split16(W[(size_t)p * NN + nb + n], h, l);
    const int kk = p >> 1, parity = p & 1;
    const int r  = ((kk >> 3) << 2) + (kk & 3);
    const int hh = (kk >> 2) & 1;
    uint32_t off = (uint32_t)k * BBUF
                 + (uint32_t)((r * BROW + hh * 16 + n) << 2) + (uint32_t)(parity << 1);
    *(uint16_t*)(g_packedW + off)         = h;
    *(uint16_t*)(g_packedW + off + BHALF) = l;
}

// ---------------- fill B buffer for layer kn via cp.async ----------------
__device__ __forceinline__ void fillB(uint32_t dstB, int kn, int tid) {
    const int nch    = (NC + kn * LW) >> 4;
    const int chunks = 4 * nch * 10;                // rows*160B / 16 per half
    const unsigned char* src = g_packedW + (size_t)kn * BBUF;
    for (int c = tid; c < chunks; c += NTHREADS) {
        asm volatile("cp.async.cg.shared.global [%0], [%1], 16;"
            :: "r"(dstB + (uint32_t)c * 16), "l"(src + (uint32_t)c * 16) : "memory");
        asm volatile("cp.async.cg.shared.global [%0], [%1], 16;"
            :: "r"(dstB + BHALF + (uint32_t)c * 16), "l"(src + BHALF + (uint32_t)c * 16) : "memory");
    }
}

// Fully-unrolled MMA loop; 6 accumulator chains (even/odd j x hh/hl/lh).
template<int NCH>
__device__ __forceinline__ void layer_mma(float chh[2][4], float chl[2][4], float clh[2][4],
                                          uint32_t a_addr, const char* bp, uint32_t bwoff) {
    #pragma unroll
    for (int j = 0; j < NCH; ++j) {
        uint32_t ahi[4], alo[4];
        ldsm_x4(ahi, a_addr + (uint32_t)j * 32);
        ldsm_x4(alo, a_addr + ABYTES + (uint32_t)j * 32);
        const char* bb = bp + (uint32_t)j * (4 * BROW * 4) + bwoff;
        uint32_t bh0 = *(const uint32_t*)(bb);
        uint32_t bh1 = *(const uint32_t*)(bb + 64);
        uint32_t bl0 = *(const uint32_t*)(bb + BHALF);
        uint32_t bl1 = *(const uint32_t*)(bb + BHALF + 64);
        const int s = j & 1;
        mma16816(chh[s], ahi, bh0, bh1);
        mma16816(chl[s], ahi, bl0, bl1);
        mma16816(clh[s], alo, bh0, bh1);
    }
}

__global__ __launch_bounds__(NTHREADS, 2)
void scm_kernel(const float* __restrict__ causes,
                const float* __restrict__ eps,
                const int*   __restrict__ act_ids,
                const int*   __restrict__ x_idx,
                const int*   __restrict__ y_idx_p,
                float*       __restrict__ out)
{
    extern __shared__ char smem[];
    const uint32_t sb = smem_u32(smem);
    int*  acts = (int*)(smem + OFF_ACTS);
    int*  xs   = (int*)(smem + OFF_XS);
    char* Ahi  = smem + OFF_AHI;
    char* Alo  = smem + OFF_ALO;

    const int tid  = threadIdx.x;
    const int lane = tid & 31;
    const int g    = lane >> 2;
    const int tig  = lane & 3;
    const int wid  = tid >> 5;
    const int rg   = wid & 3;
    const int nh   = wid >> 2;
    const int R    = rg * 16;
    const int row0 = blockIdx.x * ROWS;

    if (tid < NN) acts[tid] = act_ids[tid];
    if (tid < NF) xs[tid]   = x_idx[tid];

    // ---- init: fill B(0) from packed image; roots -> A ----
    fillB(sb + OFF_BP, 0, tid);
    asm volatile("cp.async.commit_group;" ::: "memory");

    {
        int m = tid >> 2, q = tid & 3;
        const float4* c4 = (const float4*)(causes + (size_t)(row0 + m) * NC + q * 8);
        float4 a = c4[0], b = c4[1];
        float v[8] = { a.x,a.y,a.z,a.w, b.x,b.y,b.z,b.w };
        uint32_t whi[4], wlo[4];
        #pragma unroll
        for (int i = 0; i < 4; ++i) {
            uint16_t h0, l0, h1, l1;
            float v0 = fminf(fmaxf(v[2*i],   -5.f), 5.f);
            float v1 = fminf(fmaxf(v[2*i+1], -5.f), 5.f);
            split16(v0, h0, l0); split16(v1, h1, l1);
            whi[i] = (uint32_t)h0 | ((uint32_t)h1 << 16);
            wlo[i] = (uint32_t)l0 | ((uint32_t)l1 << 16);
        }
        uint32_t base = (uint32_t)m * (AS * 2) + (uint32_t)q * 16;
        *(uint4*)(Ahi + base) = make_uint4(whi[0], whi[1], whi[2], whi[3]);
        *(uint4*)(Alo + base) = make_uint4(wlo[0], wlo[1], wlo[2], wlo[3]);
    }
    asm volatile("cp.async.wait_group 0;" ::: "memory");
    __syncthreads();

    const uint32_t a_addr = sb + OFF_AHI
                          + (uint32_t)(R + (lane & 15)) * (AS * 2)
                          + (uint32_t)((lane >> 4) * 8) * 2;
    const int bcol = nh * 8 + g;
    const uint32_t bwoff = (uint32_t)(tig * (BROW * 4) + bcol * 4);

    for (int k = 0; k < NL; ++k) {
        const int nb   = NC + k * LW;
        const int nch  = nb >> 4;
        const char* bp = smem + OFF_BP + (k & 1) * BBUF;

        // async fill of B(k+1); WAR on B((k+1)&1) safe: its layer-(k-1) readers
        // finished before the barrier that started this layer body.
        if (k < NL - 1)
            fillB(sb + OFF_BP + ((k + 1) & 1) * BBUF, k + 1, tid);
        asm volatile("cp.async.commit_group;" ::: "memory");

        // eps LDG early (consumed in epilogue)
        const int col0 = nb + nh * 8 + 2 * tig;
        float2 ev0 = *(const float2*)(eps + (size_t)(row0 + R + g)     * NN + col0);
        float2 ev1 = *(const float2*)(eps + (size_t)(row0 + R + g + 8) * NN + col0);

        // --- fully-unrolled MMA loop, 6 accumulator chains ---
        float chh[2][4] = {{0,0,0,0},{0,0,0,0}};
        float chl[2][4] = {{0,0,0,0},{0,0,0,0}};
        float clh[2][4] = {{0,0,0,0},{0,0,0,0}};
        switch (nch) {
            case 2:  layer_mma<2>(chh, chl, clh, a_addr, bp, bwoff); break;
            case 3:  layer_mma<3>(chh, chl, clh, a_addr, bp, bwoff); break;
            case 4:  layer_mma<4>(chh, chl, clh, a_addr, bp, bwoff); break;
            case 5:  layer_mma<5>(chh, chl, clh, a_addr, bp, bwoff); break;
            case 6:  layer_mma<6>(chh, chl, clh, a_addr, bp, bwoff); break;
            case 7:  layer_mma<7>(chh, chl, clh, a_addr, bp, bwoff); break;
            case 8:  layer_mma<8>(chh, chl, clh, a_addr, bp, bwoff); break;
            case 9:  layer_mma<9>(chh, chl, clh, a_addr, bp, bwoff); break;
            case 10: layer_mma<10>(chh, chl, clh, a_addr, bp, bwoff); break;
            case 11: layer_mma<11>(chh, chl, clh, a_addr, bp, bwoff); break;
            case 12: layer_mma<12>(chh, chl, clh, a_addr, bp, bwoff); break;
            case 13: layer_mma<13>(chh, chl, clh, a_addr, bp, bwoff); break;
            case 14: layer_mma<14>(chh, chl, clh, a_addr, bp, bwoff); break;
            default: layer_mma<15>(chh, chl, clh, a_addr, bp, bwoff); break;
        }

        // epilogue: z = sum(chains) + eps, activation, hi/lo split, store back to A
        {
            const int aid0 = acts[col0], aid1 = acts[col0 + 1];
            float z0 = (chh[0][0]+chh[1][0]) + (chl[0][0]+chl[1][0]) + (clh[0][0]+clh[1][0]) + ev0.x;
            float z1 = (chh[0][1]+chh[1][1]) + (chl[0][1]+chl[1][1]) + (clh[0][1]+clh[1][1]) + ev0.y;
            float z2 = (chh[0][2]+chh[1][2]) + (chl[0][2]+chl[1][2]) + (clh[0][2]+clh[1][2]) + ev1.x;
            float z3 = (chh[0][3]+chh[1][3]) + (chl[0][3]+chl[1][3]) + (clh[0][3]+clh[1][3]) + ev1.y;
            float a0 = actf(aid0, z0), a1 = actf(aid1, z1);
            float a2 = actf(aid0, z2), a3 = actf(aid1, z3);
            uint16_t h0,l0,h1,l1,h2,l2,h3,l3;
            split16(a0,h0,l0); split16(a1,h1,l1); split16(a2,h2,l2); split16(a3,h3,l3);
            uint32_t b0 = (uint32_t)(R + g)     * (AS * 2) + (uint32_t)col0 * 2;
            uint32_t b1 = (uint32_t)(R + g + 8) * (AS * 2) + (uint32_t)col0 * 2;
            *(uint32_t*)(Ahi + b0) = (uint32_t)h0 | ((uint32_t)h1 << 16);
            *(uint32_t*)(Alo + b0) = (uint32_t)l0 | ((uint32_t)l1 << 16);
            *(uint32_t*)(Ahi + b1) = (uint32_t)h2 | ((uint32_t)h3 << 16);
            *(uint32_t*)(Alo + b1) = (uint32_t)l2 | ((uint32_t)l3 << 16);
        }
        asm volatile("cp.async.wait_group 0;" ::: "memory");
        __syncthreads();   // publish A cols + B(k+1)
    }

    // ---- outputs ----
    const int yidx = y_idx_p ? *y_idx_p : (NN - 1);
    float* Xout = out;
    float* yout = out + (size_t)SEQ_LEN * NF;

    if (tid < ROWS) {
        float v = readA(Ahi, Alo, tid, yidx);
        if (v != v) v = 0.f;
        yout[row0 + tid] = v;
    }
    for (int idx = tid; idx < ROWS * NF; idx += NTHREADS) {
        int r = idx / NF, j2 = idx - r * NF;
        float v = readA(Ahi, Alo, r, xs[j2]);
        if (v != v) v = 0.f;
        v = fminf(fmaxf(v, -15.f), 15.f);
        Xout[(size_t)(row0 + r) * NF + j2] = v;
    }
}

extern "C" void kernel_launch(void* const* d_in, const int* in_sizes, int n_in,
                              void* d_out, int out_size)
{
    const float* causes  = (const float*)d_in[0];
    const float* W       = (const float*)d_in[1];
    const float* eps     = (const float*)d_in[2];
    const int*   act_ids = (const int*)d_in[3];
    const int*   x_idx   = (const int*)d_in[4];
    const int*   y_idx_p = (n_in > 5) ? (const int*)d_in[5] : nullptr;
    float*       out     = (float*)d_out;

    cudaFuncSetAttribute(scm_kernel, cudaFuncAttributeMaxDynamicSharedMemorySize, SMEM_BYTES);

    dim3 pgrid((240 * 16 + 255) / 256, NL);
    pack_kernel<<<pgrid, 256>>>(W);
    scm_kernel<<<SEQ_LEN / ROWS, NTHREADS, SMEM_BYTES>>>(
        causes, eps, act_ids, x_idx, y_idx_p, out);
    (void)in_sizes; (void)out_size;
}

// round 13
// speedup vs baseline: 1.2467x; 1.0114x over previous
#include <cuda_runtime.h>
#include <cuda_fp16.h>
#include <math.h>
#include <stdint.h>

// ---------------- problem constants ----------------
#define SEQ_LEN   65536
#define NN        256
#define NC        32
#define LW        16
#define NL        14
#define NF        200
#define ROWS      64       // M per CTA (2 CTAs/SM)
#define NTHREADS  256      // 8 warps: 4 row-groups x 2 n-halves
#define AS        264      // A row stride in fp16 elems (528 B) -> conflict-free ldmatrix

// ---------------- packed-B layout (interleaved hi/lo) ----------------
// Row r = j*4 + tig, 288 B row stride (72 u32 words; 64 used + 8 pad).
// word[n*4 + c]: c=0: hi pair kk=j*8+tig, c=1: hi pair kk+4, c=2: lo kk, c=3: lo kk+4.
// One LDS.128 at (r*288 + n*16) yields all 4 b-fragments. Conflict-free.
#define BROWB     288                       // bytes per row
#define BBUF      (60 * BROWB)              // 17280 B per layer image (rows <= 60)

// ---------------- smem map (bytes) ----------------
#define OFF_ACTS  0
#define OFF_XS    1024
#define OFF_BP    2048
#define OFF_AHI   (OFF_BP + 2 * BBUF)       // 36608
#define ABYTES    (ROWS * AS * 2)           // 33792
#define OFF_ALO   (OFF_AHI + ABYTES)        // 70400
#define SMEM_BYTES (OFF_ALO + ABYTES)       // 104192  -> 2 CTAs/SM

// Pre-packed W images, written by pack_kernel, read via cp.async.
__device__ __align__(16) unsigned char g_packedW[NL * BBUF];

// ---------------- helpers ----------------
__device__ __forceinline__ uint32_t smem_u32(const void* p) {
    uint32_t a;
    asm("{ .reg .u64 t; cvta.to.shared.u64 t, %1; cvt.u32.u64 %0, t; }" : "=r"(a) : "l"(p));
    return a;
}
__device__ __forceinline__ void ldsm_x4(uint32_t a[4], uint32_t addr) {
    asm volatile("ldmatrix.sync.aligned.m8n8.x4.shared.b16 {%0,%1,%2,%3}, [%4];"
        : "=r"(a[0]), "=r"(a[1]), "=r"(a[2]), "=r"(a[3]) : "r"(addr));
}
__device__ __forceinline__ void mma16816(float c[4], const uint32_t a[4], uint32_t b0, uint32_t b1) {
    asm volatile("mma.sync.aligned.m16n8k16.row.col.f32.f16.f16.f32 "
        "{%0,%1,%2,%3}, {%4,%5,%6,%7}, {%8,%9}, {%0,%1,%2,%3};"
        : "+f"(c[0]), "+f"(c[1]), "+f"(c[2]), "+f"(c[3])
        : "r"(a[0]), "r"(a[1]), "r"(a[2]), "r"(a[3]), "r"(b0), "r"(b1));
}
__device__ __forceinline__ void split16(float v, uint16_t& h, uint16_t& l) {
    __half hh = __float2half_rn(v);
    float  r  = v - __half2float(hh);
    __half ll = __float2half_rn(r);
    h = __half_as_ushort(hh);
    l = __half_as_ushort(ll);
}
__device__ __forceinline__ float ex2a(float x) {
    float r; asm("ex2.approx.f32 %0, %1;" : "=f"(r) : "f"(x)); return r;
}
__device__ __forceinline__ float rcpa(float x) {
    float r; asm("rcp.approx.f32 %0, %1;" : "=f"(r) : "f"(x)); return r;
}
__device__ __forceinline__ float actf(int aid, float z) {
    if (aid == 0) return z;
    if (aid == 2) return fmaxf(z, 0.f);
    if (aid == 1) {                       // tanh(z) = 1 - 2/(1+e^{2z})
        float t = ex2a(z * 2.8853900817779268f);
        return fmaf(-2.f, rcpa(t + 1.f), 1.f);
    }
    float t = ex2a(-z * 1.4426950408889634f);      // sigmoid
    return rcpa(1.f + t);
}
__device__ __forceinline__ float readA(const char* hi, const char* lo, int m, int node) {
    uint32_t b = (uint32_t)m * (AS * 2) + (uint32_t)node * 2;
    return __half2float(*(const __half*)(hi + b)) + __half2float(*(const __half*)(lo + b));
}

// ---------------- pack kernel: W -> g_packedW ----------------
__global__ void pack_kernel(const float* __restrict__ W) {
    const int k = blockIdx.y;
    const int e = blockIdx.x * 256 + threadIdx.x;   // e = p*16 + n
    const int nb = NC + k * LW;                     // parent count for layer k
    if (e >= nb * 16) return;
    const int p = e >> 4, n = e & 15;
    uint16_t h, l;
    split16(W[(size_t)p * NN + nb + n], h, l);
    const int kk = p >> 1, parity = p & 1;
    const int r  = ((kk >> 3) << 2) + (kk & 3);     // j*4 + tig
    const int hh = (kk >> 2) & 1;
    uint32_t off = (uint32_t)k * BBUF + (uint32_t)r * BROWB
                 + (uint32_t)((n * 4 + hh) << 2) + (uint32_t)(parity << 1);
    *(uint16_t*)(g_packedW + off)     = h;          // hi at word n*4+hh
    *(uint16_t*)(g_packedW + off + 8) = l;          // lo at word n*4+2+hh
}

// ---------------- fill B buffer for layer kn via cp.async ----------------
__device__ __forceinline__ void fillB(uint32_t dstB, int kn, int tid) {
    const int nch    = (NC + kn * LW) >> 4;
    const int chunks = 4 * nch * (BROWB / 16);      // rows * 18 chunks of 16B
    const unsigned char* src = g_packedW + (size_t)kn * BBUF;
    for (int c = tid; c < chunks; c += NTHREADS) {
        asm volatile("cp.async.cg.shared.global [%0], [%1], 16;"
            :: "r"(dstB + (uint32_t)c * 16), "l"(src + (uint32_t)c * 16) : "memory");
    }
}

// Fully-unrolled MMA loop; 6 accumulator chains (even/odd j x hh/hl/lh).
template<int NCH>
__device__ __forceinline__ void layer_mma(float chh[2][4], float chl[2][4], float clh[2][4],
                                          uint32_t a_addr, const char* bp, uint32_t bwoff) {
    #pragma unroll
    for (int j = 0; j < NCH; ++j) {
        uint32_t ahi[4], alo[4];
        ldsm_x4(ahi, a_addr + (uint32_t)j * 32);
        ldsm_x4(alo, a_addr + ABYTES + (uint32_t)j * 32);
        uint4 bf = *(const uint4*)(bp + (uint32_t)j * (4 * BROWB) + bwoff);  // LDS.128
        const int s = j & 1;
        mma16816(chh[s], ahi, bf.x, bf.y);
        mma16816(chl[s], ahi, bf.z, bf.w);
        mma16816(clh[s], alo, bf.x, bf.y);
    }
}

__global__ __launch_bounds__(NTHREADS, 2)
void scm_kernel(const float* __restrict__ causes,
                const float* __restrict__ eps,
                const int*   __restrict__ act_ids,
                const int*   __restrict__ x_idx,
                const int*   __restrict__ y_idx_p,
                float*       __restrict__ out)
{
    extern __shared__ char smem[];
    const uint32_t sb = smem_u32(smem);
    int*  acts = (int*)(smem + OFF_ACTS);
    int*  xs   = (int*)(smem + OFF_XS);
    char* Ahi  = smem + OFF_AHI;
    char* Alo  = smem + OFF_ALO;

    const int tid  = threadIdx.x;
    const int lane = tid & 31;
    const int g    = lane >> 2;
    const int tig  = lane & 3;
    const int wid  = tid >> 5;
    const int rg   = wid & 3;
    const int nh   = wid >> 2;
    const int R    = rg * 16;
    const int row0 = blockIdx.x * ROWS;

    if (tid < NN) acts[tid] = act_ids[tid];
    if (tid < NF) xs[tid]   = x_idx[tid];

    // ---- init: fill B(0); roots -> A ----
    fillB(sb + OFF_BP, 0, tid);
    asm volatile("cp.async.commit_group;" ::: "memory");

    {
        int m = tid >> 2, q = tid & 3;
        const float4* c4 = (const float4*)(causes + (size_t)(row0 + m) * NC + q * 8);
        float4 a = c4[0], b = c4[1];
        float v[8] = { a.x,a.y,a.z,a.w, b.x,b.y,b.z,b.w };
        uint32_t whi[4], wlo[4];
        #pragma unroll
        for (int i = 0; i < 4; ++i) {
            uint16_t h0, l0, h1, l1;
            float v0 = fminf(fmaxf(v[2*i],   -5.f), 5.f);
            float v1 = fminf(fmaxf(v[2*i+1], -5.f), 5.f);
            split16(v0, h0, l0); split16(v1, h1, l1);
            whi[i] = (uint32_t)h0 | ((uint32_t)h1 << 16);
            wlo[i] = (uint32_t)l0 | ((uint32_t)l1 << 16);
        }
        uint32_t base = (uint32_t)m * (AS * 2) + (uint32_t)q * 16;
        *(uint4*)(Ahi + base) = make_uint4(whi[0], whi[1], whi[2], whi[3]);
        *(uint4*)(Alo + base) = make_uint4(wlo[0], wlo[1], wlo[2], wlo[3]);
    }

    // eps prefetch for layer 0
    float2 ev0, ev1;
    {
        const int c0 = NC + nh * 8 + 2 * tig;
        ev0 = *(const float2*)(eps + (size_t)(row0 + R + g)     * NN + c0);
        ev1 = *(const float2*)(eps + (size_t)(row0 + R + g + 8) * NN + c0);
    }

    asm volatile("cp.async.wait_group 0;" ::: "memory");
    __syncthreads();

    const uint32_t a_addr = sb + OFF_AHI
                          + (uint32_t)(R + (lane & 15)) * (AS * 2)
                          + (uint32_t)((lane >> 4) * 8) * 2;
    const int bcol = nh * 8 + g;
    const uint32_t bwoff = (uint32_t)(tig * BROWB + bcol * 16);

    for (int k = 0; k < NL; ++k) {
        const int nb   = NC + k * LW;
        const int nch  = nb >> 4;
        const char* bp = smem + OFF_BP + (k & 1) * BBUF;

        // async fill of B(k+1) (WAR safe: prior readers done before last barrier)
        if (k < NL - 1)
            fillB(sb + OFF_BP + ((k + 1) & 1) * BBUF, k + 1, tid);
        asm volatile("cp.async.commit_group;" ::: "memory");

        // prefetch NEXT layer's eps (consumed after next layer's MMAs)
        float2 evn0, evn1;
        if (k < NL - 1) {
            const int cn = nb + LW + nh * 8 + 2 * tig;
            evn0 = *(const float2*)(eps + (size_t)(row0 + R + g)     * NN + cn);
            evn1 = *(const float2*)(eps + (size_t)(row0 + R + g + 8) * NN + cn);
        }

        // --- fully-unrolled MMA loop, 6 accumulator chains ---
        float chh[2][4] = {{0,0,0,0},{0,0,0,0}};
        float chl[2][4] = {{0,0,0,0},{0,0,0,0}};
        float clh[2][4] = {{0,0,0,0},{0,0,0,0}};
        switch (nch) {
            case 2:  layer_mma<2>(chh, chl, clh, a_addr, bp, bwoff); break;
            case 3:  layer_mma<3>(chh, chl, clh, a_addr, bp, bwoff); break;
            case 4:  layer_mma<4>(chh, chl, clh, a_addr, bp, bwoff); break;
            case 5:  layer_mma<5>(chh, chl, clh, a_addr, bp, bwoff); break;
            case 6:  layer_mma<6>(chh, chl, clh, a_addr, bp, bwoff); break;
            case 7:  layer_mma<7>(chh, chl, clh, a_addr, bp, bwoff); break;
            case 8:  layer_mma<8>(chh, chl, clh, a_addr, bp, bwoff); break;
            case 9:  layer_mma<9>(chh, chl, clh, a_addr, bp, bwoff); break;
            case 10: layer_mma<10>(chh, chl, clh, a_addr, bp, bwoff); break;
            case 11: layer_mma<11>(chh, chl, clh, a_addr, bp, bwoff); break;
            case 12: layer_mma<12>(chh, chl, clh, a_addr, bp, bwoff); break;
            case 13: layer_mma<13>(chh, chl, clh, a_addr, bp, bwoff); break;
            case 14: layer_mma<14>(chh, chl, clh, a_addr, bp, bwoff); break;
            default: layer_mma<15>(chh, chl, clh, a_addr, bp, bwoff); break;
        }

        // epilogue: z = sum(chains) + eps, activation, hi/lo split, store back to A
        {
            const int col0 = nb + nh * 8 + 2 * tig;
            const int aid0 = acts[col0], aid1 = acts[col0 + 1];
            float z0 = (chh[0][0]+chh[1][0]) + (chl[0][0]+chl[1][0]) + (clh[0][0]+clh[1][0]) + ev0.x;
            float z1 = (chh[0][1]+chh[1][1]) + (chl[0][1]+chl[1][1]) + (clh[0][1]+clh[1][1]) + ev0.y;
            float z2 = (chh[0][2]+chh[1][2]) + (chl[0][2]+chl[1][2]) + (clh[0][2]+clh[1][2]) + ev1.x;
            float z3 = (chh[0][3]+chh[1][3]) + (chl[0][3]+chl[1][3]) + (clh[0][3]+clh[1][3]) + ev1.y;
            float a0 = actf(aid0, z0), a1 = actf(aid1, z1);
            float a2 = actf(aid0, z2), a3 = actf(aid1, z3);
            uint16_t h0,l0,h1,l1,h2,l2,h3,l3;
            split16(a0,h0,l0); split16(a1,h1,l1); split16(a2,h2,l2); split16(a3,h3,l3);
            uint32_t b0 = (uint32_t)(R + g)     * (AS * 2) + (uint32_t)col0 * 2;
            uint32_t b1 = (uint32_t)(R + g + 8) * (AS * 2) + (uint32_t)col0 * 2;
            *(uint32_t*)(Ahi + b0) = (uint32_t)h0 | ((uint32_t)h1 << 16);
            *(uint32_t*)(Alo + b0) = (uint32_t)l0 | ((uint32_t)l1 << 16);
            *(uint32_t*)(Ahi + b1) = (uint32_t)h2 | ((uint32_t)h3 << 16);
            *(uint32_t*)(Alo + b1) = (uint32_t)l2 | ((uint32_t)l3 << 16);
        }
        ev0 = evn0; ev1 = evn1;

        asm volatile("cp.async.wait_group 0;" ::: "memory");
        __syncthreads();   // publish A cols + B(k+1)
    }

    // ---- outputs ----
    const int yidx = y_idx_p ? *y_idx_p : (NN - 1);
    float* Xout = out;
    float* yout = out + (size_t)SEQ_LEN * NF;

    if (tid < ROWS) {
        float v = readA(Ahi, Alo, tid, yidx);
        if (v != v) v = 0.f;
        yout[row0 + tid] = v;
    }
    for (int idx = tid; idx < ROWS * NF; idx += NTHREADS) {
        int r = idx / NF, j2 = idx - r * NF;
        float v = readA(Ahi, Alo, r, xs[j2]);
        if (v != v) v = 0.f;
        v = fminf(fmaxf(v, -15.f), 15.f);
        Xout[(size_t)(row0 + r) * NF + j2] = v;
    }
}

extern "C" void kernel_launch(void* const* d_in, const int* in_sizes, int n_in,
                              void* d_out, int out_size)
{
    const float* causes  = (const float*)d_in[0];
    const float* W       = (const float*)d_in[1];
    const float* eps     = (const float*)d_in[2];
    const int*   act_ids = (const int*)d_in[3];
    const int*   x_idx   = (const int*)d_in[4];
    const int*   y_idx_p = (n_in > 5) ? (const int*)d_in[5] : nullptr;
    float*       out     = (float*)d_out;

    cudaFuncSetAttribute(scm_kernel, cudaFuncAttributeMaxDynamicSharedMemorySize, SMEM_BYTES);

    dim3 pgrid((240 * 16 + 255) / 256, NL);
    pack_kernel<<<pgrid, 256>>>(W);
    scm_kernel<<<SEQ_LEN / ROWS, NTHREADS, SMEM_BYTES>>>(
        causes, eps, act_ids, x_idx, y_idx_p, out);
    (void)in_sizes; (void)out_size;
}

// round 14
// speedup vs baseline: 1.2493x; 1.0021x over previous
#include <cuda_runtime.h>
#include <cuda_fp16.h>
#include <math.h>
#include <stdint.h>

// ---------------- problem constants ----------------
#define SEQ_LEN   65536
#define NN        256
#define NC        32
#define LW        16
#define NL        14
#define NF        200
#define ROWS      64       // M per CTA (2 CTAs/SM)
#define NTHREADS  256      // 8 warps: 4 row-groups x 2 n-halves
#define AS        264      // A row stride in fp16 elems (528 B) -> conflict-free ldmatrix

// ---------------- packed-B layout (interleaved hi/lo) ----------------
// Row r = j*4 + tig, 288 B row stride (72 u32 words; 64 used + 8 pad).
// word[n*4 + c]: c=0: hi pair kk=j*8+tig, c=1: hi pair kk+4, c=2: lo kk, c=3: lo kk+4.
// One LDS.128 at (r*288 + n*16) yields all 4 b-fragments. Conflict-free.
#define BROWB     288                       // bytes per row
#define BBUF      (60 * BROWB)              // 17280 B per layer image (rows <= 60)

// ---------------- smem map (bytes) ----------------
#define OFF_ACTS  0
#define OFF_XS    1024
#define OFF_BP    2048
#define OFF_AHI   (OFF_BP + 2 * BBUF)       // 36608
#define ABYTES    (ROWS * AS * 2)           // 33792
#define OFF_ALO   (OFF_AHI + ABYTES)        // 70400
#define SMEM_BYTES (OFF_ALO + ABYTES)       // 104192  -> 2 CTAs/SM

// Pre-packed W images, written by pack_kernel, read via cp.async.
__device__ __align__(16) unsigned char g_packedW[NL * BBUF];

// ---------------- helpers ----------------
__device__ __forceinline__ uint32_t smem_u32(const void* p) {
    uint32_t a;
    asm("{ .reg .u64 t; cvta.to.shared.u64 t, %1; cvt.u32.u64 %0, t; }" : "=r"(a) : "l"(p));
    return a;
}
__device__ __forceinline__ void ldsm_x4(uint32_t a[4], uint32_t addr) {
    asm volatile("ldmatrix.sync.aligned.m8n8.x4.shared.b16 {%0,%1,%2,%3}, [%4];"
        : "=r"(a[0]), "=r"(a[1]), "=r"(a[2]), "=r"(a[3]) : "r"(addr));
}
__device__ __forceinline__ void mma16816(float c[4], const uint32_t a[4], uint32_t b0, uint32_t b1) {
    asm volatile("mma.sync.aligned.m16n8k16.row.col.f32.f16.f16.f32 "
        "{%0,%1,%2,%3}, {%4,%5,%6,%7}, {%8,%9}, {%0,%1,%2,%3};"
        : "+f"(c[0]), "+f"(c[1]), "+f"(c[2]), "+f"(c[3])
        : "r"(a[0]), "r"(a[1]), "r"(a[2]), "r"(a[3]), "r"(b0), "r"(b1));
}
__device__ __forceinline__ void split16(float v, uint16_t& h, uint16_t& l) {
    __half hh = __float2half_rn(v);
    float  r  = v - __half2float(hh);
    __half ll = __float2half_rn(r);
    h = __half_as_ushort(hh);
    l = __half_as_ushort(ll);
}
__device__ __forceinline__ float ex2a(float x) {
    float r; asm("ex2.approx.f32 %0, %1;" : "=f"(r) : "f"(x)); return r;
}
__device__ __forceinline__ float rcpa(float x) {
    float r; asm("rcp.approx.f32 %0, %1;" : "=f"(r) : "f"(x)); return r;
}
__device__ __forceinline__ float actf(int aid, float z) {
    if (aid == 0) return z;
    if (aid == 2) return fmaxf(z, 0.f);
    if (aid == 1) {                       // tanh(z) = 1 - 2/(1+e^{2z})
        float t = ex2a(z * 2.8853900817779268f);
        return fmaf(-2.f, rcpa(t + 1.f), 1.f);
    }
    float t = ex2a(-z * 1.4426950408889634f);      // sigmoid
    return rcpa(1.f + t);
}
__device__ __forceinline__ float readA(const char* hi, const char* lo, int m, int node) {
    uint32_t b = (uint32_t)m * (AS * 2) + (uint32_t)node * 2;
    return __half2float(*(const __half*)(hi + b)) + __half2float(*(const __half*)(lo + b));
}

// ---------------- pack kernel: W -> g_packedW ----------------
__global__ void pack_kernel(const float* __restrict__ W) {
    const int k = blockIdx.y;
    const int e = blockIdx.x * 256 + threadIdx.x;   // e = p*16 + n
    const int nb = NC + k * LW;                     // parent count for layer k
    if (e >= nb * 16) return;
    const int p = e >> 4, n = e & 15;
    uint16_t h, l;
    split16(W[(size_t)p * NN + nb + n], h, l);
    const int kk = p >> 1, parity = p & 1;
    const int r  = ((kk >> 3) << 2) + (kk & 3);     // j*4 + tig
    const int hh = (kk >> 2) & 1;
    uint32_t off = (uint32_t)k * BBUF + (uint32_t)r * BROWB
                 + (uint32_t)((n * 4 + hh) << 2) + (uint32_t)(parity << 1);
    *(uint16_t*)(g_packedW + off)     = h;          // hi at word n*4+hh
    *(uint16_t*)(g_packedW + off + 8) = l;          // lo at word n*4+2+hh
}

// ---------------- fill B buffer for layer kn via cp.async ----------------
__device__ __forceinline__ void fillB(uint32_t dstB, int kn, int tid) {
    const int nch    = (NC + kn * LW) >> 4;
    const int chunks = 4 * nch * (BROWB / 16);      // rows * 18 chunks of 16B
    const unsigned char* src = g_packedW + (size_t)kn * BBUF;
    for (int c = tid; c < chunks; c += NTHREADS) {
        asm volatile("cp.async.cg.shared.global [%0], [%1], 16;"
            :: "r"(dstB + (uint32_t)c * 16), "l"(src + (uint32_t)c * 16) : "memory");
    }
}

// Fully-unrolled MMA loop; 6 accumulator chains (even/odd j x hh/hl/lh).
template<int NCH>
__device__ __forceinline__ void layer_mma(float chh[2][4], float chl[2][4], float clh[2][4],
                                          uint32_t a_addr, const char* bp, uint32_t bwoff) {
    #pragma unroll
    for (int j = 0; j < NCH; ++j) {
        uint32_t ahi[4], alo[4];
        ldsm_x4(ahi, a_addr + (uint32_t)j * 32);
        ldsm_x4(alo, a_addr + ABYTES + (uint32_t)j * 32);
        uint4 bf = *(const uint4*)(bp + (uint32_t)j * (4 * BROWB) + bwoff);  // LDS.128
        const int s = j & 1;
        mma16816(chh[s], ahi, bf.x, bf.y);
        mma16816(chl[s], ahi, bf.z, bf.w);
        mma16816(clh[s], alo, bf.x, bf.y);
    }
}

__global__ __launch_bounds__(NTHREADS, 2)
void scm_kernel(const float* __restrict__ causes,
                const float* __restrict__ eps,
                const int*   __restrict__ act_ids,
                const int*   __restrict__ x_idx,
                const int*   __restrict__ y_idx_p,
                float*       __restrict__ out)
{
    extern __shared__ char smem[];
    const uint32_t sb = smem_u32(smem);
    int*  acts = (int*)(smem + OFF_ACTS);
    int*  xs   = (int*)(smem + OFF_XS);
    char* Ahi  = smem + OFF_AHI;
    char* Alo  = smem + OFF_ALO;

    const int tid  = threadIdx.x;
    const int lane = tid & 31;
    const int g    = lane >> 2;
    const int tig  = lane & 3;
    const int wid  = tid >> 5;
    const int rg   = wid & 3;
    const int nh   = wid >> 2;
    const int R    = rg * 16;
    const int row0 = blockIdx.x * ROWS;

    if (tid < NN) acts[tid] = act_ids[tid];
    if (tid < NF) xs[tid]   = x_idx[tid];

    // ---- init: fill B(0); roots -> A ----
    fillB(sb + OFF_BP, 0, tid);
    asm volatile("cp.async.commit_group;" ::: "memory");

    {
        int m = tid >> 2, q = tid & 3;
        const float4* c4 = (const float4*)(causes + (size_t)(row0 + m) * NC + q * 8);
        float4 a = c4[0], b = c4[1];
        float v[8] = { a.x,a.y,a.z,a.w, b.x,b.y,b.z,b.w };
        uint32_t whi[4], wlo[4];
        #pragma unroll
        for (int i = 0; i < 4; ++i) {
            uint16_t h0, l0, h1, l1;
            float v0 = fminf(fmaxf(v[2*i],   -5.f), 5.f);
            float v1 = fminf(fmaxf(v[2*i+1], -5.f), 5.f);
            split16(v0, h0, l0); split16(v1, h1, l1);
            whi[i] = (uint32_t)h0 | ((uint32_t)h1 << 16);
            wlo[i] = (uint32_t)l0 | ((uint32_t)l1 << 16);
        }
        uint32_t base = (uint32_t)m * (AS * 2) + (uint32_t)q * 16;
        *(uint4*)(Ahi + base) = make_uint4(whi[0], whi[1], whi[2], whi[3]);
        *(uint4*)(Alo + base) = make_uint4(wlo[0], wlo[1], wlo[2], wlo[3]);
    }

    // eps prefetch for layer 0
    float2 ev0, ev1;
    {
        const int c0 = NC + nh * 8 + 2 * tig;
        ev0 = *(const float2*)(eps + (size_t)(row0 + R + g)     * NN + c0);
        ev1 = *(const float2*)(eps + (size_t)(row0 + R + g + 8) * NN + c0);
    }

    asm volatile("cp.async.wait_group 0;" ::: "memory");
    __syncthreads();

    const uint32_t a_addr = sb + OFF_AHI
                          + (uint32_t)(R + (lane & 15)) * (AS * 2)
                          + (uint32_t)((lane >> 4) * 8) * 2;
    const int bcol = nh * 8 + g;
    const uint32_t bwoff = (uint32_t)(tig * BROWB + bcol * 16);

    for (int k = 0; k < NL; ++k) {
        const int nb   = NC + k * LW;
        const int nch  = nb >> 4;
        const char* bp = smem + OFF_BP + (k & 1) * BBUF;

        // async fill of B(k+1) (WAR safe: prior readers done before last barrier)
        if (k < NL - 1)
            fillB(sb + OFF_BP + ((k + 1) & 1) * BBUF, k + 1, tid);
        asm volatile("cp.async.commit_group;" ::: "memory");

        // prefetch NEXT layer's eps (consumed after next layer's MMAs)
        float2 evn0, evn1;
        if (k < NL - 1) {
            const int cn = nb + LW + nh * 8 + 2 * tig;
            evn0 = *(const float2*)(eps + (size_t)(row0 + R + g)     * NN + cn);
            evn1 = *(const float2*)(eps + (size_t)(row0 + R + g + 8) * NN + cn);
        }

        // --- fully-unrolled MMA loop, 6 accumulator chains ---
        float chh[2][4] = {{0,0,0,0},{0,0,0,0}};
        float chl[2][4] = {{0,0,0,0},{0,0,0,0}};
        float clh[2][4] = {{0,0,0,0},{0,0,0,0}};
        switch (nch) {
            case 2:  layer_mma<2>(chh, chl, clh, a_addr, bp, bwoff); break;
            case 3:  layer_mma<3>(chh, chl, clh, a_addr, bp, bwoff); break;
            case 4:  layer_mma<4>(chh, chl, clh, a_addr, bp, bwoff); break;
            case 5:  layer_mma<5>(chh, chl, clh, a_addr, bp, bwoff); break;
            case 6:  layer_mma<6>(chh, chl, clh, a_addr, bp, bwoff); break;
            case 7:  layer_mma<7>(chh, chl, clh, a_addr, bp, bwoff); break;
            case 8:  layer_mma<8>(chh, chl, clh, a_addr, bp, bwoff); break;
            case 9:  layer_mma<9>(chh, chl, clh, a_addr, bp, bwoff); break;
            case 10: layer_mma<10>(chh, chl, clh, a_addr, bp, bwoff); break;
            case 11: layer_mma<11>(chh, chl, clh, a_addr, bp, bwoff); break;
            case 12: layer_mma<12>(chh, chl, clh, a_addr, bp, bwoff); break;
            case 13: layer_mma<13>(chh, chl, clh, a_addr, bp, bwoff); break;
            case 14: layer_mma<14>(chh, chl, clh, a_addr, bp, bwoff); break;
            default: layer_mma<15>(chh, chl, clh, a_addr, bp, bwoff); break;
        }

        // epilogue: z = sum(chains) + eps, activation, hi/lo split, store back to A
        {
            const int col0 = nb + nh * 8 + 2 * tig;
            const int aid0 = acts[col0], aid1 = acts[col0 + 1];
            float z0 = (chh[0][0]+chh[1][0]) + (chl[0][0]+chl[1][0]) + (clh[0][0]+clh[1][0]) + ev0.x;
            float z1 = (chh[0][1]+chh[1][1]) + (chl[0][1]+chl[1][1]) + (clh[0][1]+clh[1][1]) + ev0.y;
            float z2 = (chh[0][2]+chh[1][2]) + (chl[0][2]+chl[1][2]) + (clh[0][2]+clh[1][2]) + ev1.x;
            float z3 = (chh[0][3]+chh[1][3]) + (chl[0][3]+chl[1][3]) + (clh[0][3]+clh[1][3]) + ev1.y;
            float a0 = actf(aid0, z0), a1 = actf(aid1, z1);
            float a2 = actf(aid0, z2), a3 = actf(aid1, z3);
            uint16_t h0,l0,h1,l1,h2,l2,h3,l3;
            split16(a0,h0,l0); split16(a1,h1,l1); split16(a2,h2,l2); split16(a3,h3,l3);
            uint32_t b0 = (uint32_t)(R + g)     * (AS * 2) + (uint32_t)col0 * 2;
            uint32_t b1 = (uint32_t)(R + g + 8) * (AS * 2) + (uint32_t)col0 * 2;
            *(uint32_t*)(Ahi + b0) = (uint32_t)h0 | ((uint32_t)h1 << 16);
            *(uint32_t*)(Alo + b0) = (uint32_t)l0 | ((uint32_t)l1 << 16);
            *(uint32_t*)(Ahi + b1) = (uint32_t)h2 | ((uint32_t)h3 << 16);
            *(uint32_t*)(Alo + b1) = (uint32_t)l2 | ((uint32_t)l3 << 16);
        }
        ev0 = evn0; ev1 = evn1;

        asm volatile("cp.async.wait_group 0;" ::: "memory");
        __syncthreads();   // publish A cols + B(k+1)
    }

    // ---- outputs ----
    const int yidx = y_idx_p ? *y_idx_p : (NN - 1);
    float* Xout = out;
    float* yout = out + (size_t)SEQ_LEN * NF;

    if (tid < ROWS) {
        float v = readA(Ahi, Alo, tid, yidx);
        if (v != v) v = 0.f;
        yout[row0 + tid] = v;
    }
    for (int idx = tid; idx < ROWS * NF; idx += NTHREADS) {
        int r = idx / NF, j2 = idx - r * NF;
        float v = readA(Ahi, Alo, r, xs[j2]);
        if (v != v) v = 0.f;
        v = fminf(fmaxf(v, -15.f), 15.f);
        Xout[(size_t)(row0 + r) * NF + j2] = v;
    }
}

extern "C" void kernel_launch(void* const* d_in, const int* in_sizes, int n_in,
                              void* d_out, int out_size)
{
    const float* causes  = (const float*)d_in[0];
    const float* W       = (const float*)d_in[1];
    const float* eps     = (const float*)d_in[2];
    const int*   act_ids = (const int*)d_in[3];
    const int*   x_idx   = (const int*)d_in[4];
    const int*   y_idx_p = (n_in > 5) ? (const int*)d_in[5] : nullptr;
    float*       out     = (float*)d_out;

    cudaFuncSetAttribute(scm_kernel, cudaFuncAttributeMaxDynamicSharedMemorySize, SMEM_BYTES);

    dim3 pgrid((240 * 16 + 255) / 256, NL);
    pack_kernel<<<pgrid, 256>>>(W);
    scm_kernel<<<SEQ_LEN / ROWS, NTHREADS, SMEM_BYTES>>>(
        causes, eps, act_ids, x_idx, y_idx_p, out);
    (void)in_sizes; (void)out_size;
}